// round 2
// baseline (speedup 1.0000x reference)
#include <cuda_runtime.h>

#define NN 200000
#define NE 3200000
#define F  30
#define FS 32          // padded feature stride (128B rows)
#define CHUNK 1024
#define NB ((NN + CHUNK - 1) / CHUNK)   // 196 scan blocks

// ---- scratch (device globals; no allocation allowed) ----
__device__ int   g_is64;
__device__ int   g_src[NE];
__device__ int   g_dst[NE];
__device__ int   g_deg[NN];
__device__ int   g_off[NN];
__device__ int   g_cursor[NN];
__device__ float g_dinv[NN];
__device__ int   g_csr[NE];
__device__ float g_feat[NN * FS];   // pre-scaled transformed features g = (XW)*dinv
__device__ float g_cat[NN * FS];    // concat buffer [h(30), x(2)]
__device__ float g_scal[NN];        // layer-3 scalar features
__device__ int   g_bsum[256];

// ---------------- edge dtype detect + convert ----------------

__global__ void k_detect(const void* __restrict__ ei, int E) {
    if (blockIdx.x == 0 && threadIdx.x == 0) {
        const long long* p = (const long long*)ei;
        int ok64 = 1;
        int n = (E < 64) ? E : 64;
        for (int i = 0; i < n; i++) {
            long long v = p[i];
            if (v < 0 || v >= NN) { ok64 = 0; break; }
        }
        g_is64 = ok64;
    }
}

__global__ void k_cvt(const void* __restrict__ ei, int E) {
    int is64 = g_is64;
    for (int e = blockIdx.x * blockDim.x + threadIdx.x; e < E;
         e += gridDim.x * blockDim.x) {
        int s, d;
        if (is64) {
            s = (int)((const long long*)ei)[e];
            d = (int)((const long long*)ei)[E + e];
        } else {
            s = ((const int*)ei)[e];
            d = ((const int*)ei)[E + e];
        }
        // defensive clamp (invalid -> self-edge at node 0; avoids UB)
        if ((unsigned)s >= NN) s = 0;
        if ((unsigned)d >= NN) d = 0;
        g_src[e] = s;
        g_dst[e] = d;
    }
}

// ---------------- CSR build ----------------

__global__ void k_zero() {
    int i = blockIdx.x * blockDim.x + threadIdx.x;
    if (i < NN) g_deg[i] = 0;
}

__global__ void k_hist(int E) {
    for (int e = blockIdx.x * blockDim.x + threadIdx.x; e < E;
         e += gridDim.x * blockDim.x) {
        atomicAdd(&g_deg[g_dst[e]], 1);
    }
}

__global__ void k_bsum() {   // grid NB, block 256
    __shared__ int sh[256];
    int base = blockIdx.x * CHUNK;
    int s = 0;
    for (int j = threadIdx.x; j < CHUNK; j += 256) {
        int i = base + j;
        if (i < NN) s += g_deg[i];
    }
    sh[threadIdx.x] = s;
    __syncthreads();
    for (int st = 128; st > 0; st >>= 1) {
        if (threadIdx.x < st) sh[threadIdx.x] += sh[threadIdx.x + st];
        __syncthreads();
    }
    if (threadIdx.x == 0) g_bsum[blockIdx.x] = sh[0];
}

__global__ void k_scansum(int nb) {   // 1 block
    if (threadIdx.x == 0) {
        int acc = 0;
        for (int b = 0; b < nb; b++) {
            int v = g_bsum[b];
            g_bsum[b] = acc;
            acc += v;
        }
    }
}

__global__ void k_scan() {   // grid NB, block 1024; exclusive scan + dinv
    __shared__ int sh[CHUNK];
    int i = blockIdx.x * CHUNK + threadIdx.x;
    int v = (i < NN) ? g_deg[i] : 0;
    sh[threadIdx.x] = v;
    __syncthreads();
    for (int st = 1; st < CHUNK; st <<= 1) {
        int t = (threadIdx.x >= st) ? sh[threadIdx.x - st] : 0;
        __syncthreads();
        sh[threadIdx.x] += t;
        __syncthreads();
    }
    if (i < NN) {
        int off = g_bsum[blockIdx.x] + sh[threadIdx.x] - v;  // exclusive
        g_off[i] = off;
        g_cursor[i] = off;
        g_dinv[i] = rsqrtf((float)(v + 1));   // +1 self-loop; always > 0
    }
}

__global__ void k_scatter(int E) {
    for (int e = blockIdx.x * blockDim.x + threadIdx.x; e < E;
         e += gridDim.x * blockDim.x) {
        int d = g_dst[e];
        int pos = atomicAdd(&g_cursor[d], 1);
        g_csr[pos] = g_src[e];
    }
}

// ---------------- layer transforms ----------------

// g = (x @ W1) * dinv  ;  x:[N,2], W1:[2,30]
__global__ void k_t1(const float* __restrict__ x, const float* __restrict__ W1) {
    __shared__ float w[64];
    if (threadIdx.x < 60) w[threadIdx.x] = W1[threadIdx.x];
    __syncthreads();
    int t = blockIdx.x * blockDim.x + threadIdx.x;
    if (t >= NN * FS) return;
    int i = t >> 5, f = t & 31;
    float v = 0.f;
    if (f < F) v = (x[2 * i] * w[f] + x[2 * i + 1] * w[30 + f]) * g_dinv[i];
    g_feat[t] = v;
}

// g = (cat @ W2) * dinv ;  cat:[N,32], W2:[32,30]
__global__ void k_t2(const float* __restrict__ W2) {
    __shared__ float w[32 * 30];
    for (int j = threadIdx.x; j < 960; j += blockDim.x) w[j] = W2[j];
    __syncthreads();
    int t = blockIdx.x * blockDim.x + threadIdx.x;
    if (t >= NN * FS) return;
    int i = t >> 5, f = t & 31;
    float v = 0.f;
    if (f < F) {
        const float* row = &g_cat[i * FS];
        float acc = 0.f;
#pragma unroll
        for (int k = 0; k < 32; k++) acc = fmaf(row[k], w[k * 30 + f], acc);
        v = acc * g_dinv[i];
    }
    g_feat[t] = v;
}

// g3 = (cat @ W3) * dinv ; W3:[32,1]
__global__ void k_t3(const float* __restrict__ W3) {
    __shared__ float w[32];
    if (threadIdx.x < 32) w[threadIdx.x] = W3[threadIdx.x];
    __syncthreads();
    int i = blockIdx.x * blockDim.x + threadIdx.x;
    if (i >= NN) return;
    const float* row = &g_cat[i * FS];
    float acc = 0.f;
#pragma unroll
    for (int k = 0; k < 32; k++) acc = fmaf(row[k], w[k], acc);
    g_scal[i] = acc * g_dinv[i];
}

// ---------------- aggregation ----------------

// warp per node: cat[d] = [relu(dinv[d]*(sum g[src] + g[d]) + b) (30), x[d] (2)]
__global__ void k_agg(const float* __restrict__ x, const float* __restrict__ b) {
    int d = (blockIdx.x * blockDim.x + threadIdx.x) >> 5;
    int lane = threadIdx.x & 31;
    if (d >= NN) return;
    float acc = g_feat[d * FS + lane];   // self-loop term
    int start = g_off[d], cnt = g_deg[d];
    for (int e0 = 0; e0 < cnt; e0 += 32) {
        int idx = e0 + lane;
        int s = (idx < cnt) ? g_csr[start + idx] : 0;
        int m = min(32, cnt - e0);
        for (int j = 0; j < m; j++) {
            int sj = __shfl_sync(0xffffffffu, s, j);
            acc += g_feat[sj * FS + lane];
        }
    }
    float out;
    if (lane < F) out = fmaxf(fmaf(acc, g_dinv[d], b[lane]), 0.f);
    else          out = x[2 * d + (lane - 30)];
    g_cat[d * FS + lane] = out;
}

// final: out[d] = dinv[d]*(sum g3[src] + g3[d]) + b3
__global__ void k_agg3(const float* __restrict__ b3, float* __restrict__ out) {
    int d = (blockIdx.x * blockDim.x + threadIdx.x) >> 5;
    int lane = threadIdx.x & 31;
    if (d >= NN) return;
    int start = g_off[d], cnt = g_deg[d];
    float acc = 0.f;
    for (int idx = lane; idx < cnt; idx += 32)
        acc += g_scal[g_csr[start + idx]];
#pragma unroll
    for (int st = 16; st > 0; st >>= 1)
        acc += __shfl_xor_sync(0xffffffffu, acc, st);
    if (lane == 0) out[d] = g_dinv[d] * (acc + g_scal[d]) + b3[0];
}

// ---------------- launch ----------------

extern "C" void kernel_launch(void* const* d_in, const int* in_sizes, int n_in,
                              void* d_out, int out_size) {
    const float* x  = (const float*)d_in[0];
    const void*  ei = d_in[1];
    const float* W1 = (const float*)d_in[2];
    const float* b1 = (const float*)d_in[3];
    const float* W2 = (const float*)d_in[4];
    const float* b2 = (const float*)d_in[5];
    const float* W3 = (const float*)d_in[6];
    const float* b3 = (const float*)d_in[7];
    float* out = (float*)d_out;

    int E = in_sizes[1] / 2;
    if (E > NE) E = NE;

    // edge dtype detect + convert to int32 staging
    k_detect<<<1, 32>>>(ei, E);
    k_cvt<<<2048, 256>>>(ei, E);

    // CSR build
    k_zero<<<(NN + 255) / 256, 256>>>();
    k_hist<<<1024, 256>>>(E);
    k_bsum<<<NB, 256>>>();
    k_scansum<<<1, 32>>>(NB);
    k_scan<<<NB, CHUNK>>>();
    k_scatter<<<2048, 256>>>(E);

    int tN = (NN * FS + 255) / 256;       // transform grid (N*32 threads)
    int aN = (NN * 32 + 255) / 256;       // warp-per-node grid

    // layer 1
    k_t1<<<tN, 256>>>(x, W1);
    k_agg<<<aN, 256>>>(x, b1);
    // layer 2
    k_t2<<<tN, 256>>>(W2);
    k_agg<<<aN, 256>>>(x, b2);
    // layer 3
    k_t3<<<(NN + 255) / 256, 256>>>(W3);
    k_agg3<<<aN, 256>>>(b3, out);
}

// round 3
// speedup vs baseline: 1.1433x; 1.1433x over previous
#include <cuda_runtime.h>

#define NN 200000
#define NE 3200000
#define F  30
#define FS 32          // padded feature stride (128B rows)
#define CHUNK 1024
#define NB ((NN + CHUNK - 1) / CHUNK)   // 196 scan blocks

// ---- scratch (device globals; no allocation allowed) ----
__device__ int   g_is64;
__device__ int   g_src[NE];
__device__ int   g_dst[NE];
__device__ int   g_deg[NN];
__device__ int   g_off[NN];
__device__ int   g_cursor[NN];
__device__ float g_dinv[NN];
__device__ float g_xs[NN * 2];      // x * dinv (layer-1 aggregation operand)
__device__ int   g_csr[NE];
__device__ float g_feat[NN * FS];   // pre-scaled transformed features (layer 2)
__device__ float g_cat[NN * FS];    // concat buffer [h(30), x(2)]
__device__ float g_scal[NN];        // layer-3 scalar features
__device__ int   g_bsum[256];

// ---------------- init: zero degrees + dtype detect ----------------

__global__ void k_init(const void* __restrict__ ei, int E) {
    int i = blockIdx.x * blockDim.x + threadIdx.x;
    if (i < NN) g_deg[i] = 0;
    if (i == 0) {
        const long long* p = (const long long*)ei;
        int ok64 = 1;
        int n = (E < 64) ? E : 64;
        for (int k = 0; k < n; k++) {
            long long v = p[k];
            if (v < 0 || v >= NN) { ok64 = 0; break; }
        }
        g_is64 = ok64;
    }
}

// ---------------- fused convert + histogram ----------------

__global__ void k_cvt_hist(const void* __restrict__ ei, int E) {
    int is64 = g_is64;
    for (int e = blockIdx.x * blockDim.x + threadIdx.x; e < E;
         e += gridDim.x * blockDim.x) {
        int s, d;
        if (is64) {
            s = (int)((const long long*)ei)[e];
            d = (int)((const long long*)ei)[E + e];
        } else {
            s = ((const int*)ei)[e];
            d = ((const int*)ei)[E + e];
        }
        if ((unsigned)s >= NN) s = 0;
        if ((unsigned)d >= NN) d = 0;
        g_src[e] = s;
        g_dst[e] = d;
        atomicAdd(&g_deg[d], 1);
    }
}

// ---------------- scan (offsets + dinv + xs) ----------------

__global__ void k_bsum() {   // grid NB, block 256
    __shared__ int sh[256];
    int base = blockIdx.x * CHUNK;
    int s = 0;
    for (int j = threadIdx.x; j < CHUNK; j += 256) {
        int i = base + j;
        if (i < NN) s += g_deg[i];
    }
    sh[threadIdx.x] = s;
    __syncthreads();
    for (int st = 128; st > 0; st >>= 1) {
        if (threadIdx.x < st) sh[threadIdx.x] += sh[threadIdx.x + st];
        __syncthreads();
    }
    if (threadIdx.x == 0) g_bsum[blockIdx.x] = sh[0];
}

__global__ void k_scansum(int nb) {   // 1 block
    if (threadIdx.x == 0) {
        int acc = 0;
        for (int b = 0; b < nb; b++) {
            int v = g_bsum[b];
            g_bsum[b] = acc;
            acc += v;
        }
    }
}

__global__ void k_scan(const float* __restrict__ x) {  // grid NB, block 1024
    __shared__ int sh[CHUNK];
    int i = blockIdx.x * CHUNK + threadIdx.x;
    int v = (i < NN) ? g_deg[i] : 0;
    sh[threadIdx.x] = v;
    __syncthreads();
    for (int st = 1; st < CHUNK; st <<= 1) {
        int t = (threadIdx.x >= st) ? sh[threadIdx.x - st] : 0;
        __syncthreads();
        sh[threadIdx.x] += t;
        __syncthreads();
    }
    if (i < NN) {
        int off = g_bsum[blockIdx.x] + sh[threadIdx.x] - v;  // exclusive
        g_off[i] = off;
        g_cursor[i] = off;
        float di = rsqrtf((float)(v + 1));   // +1 self-loop
        g_dinv[i] = di;
        g_xs[2 * i]     = x[2 * i]     * di;
        g_xs[2 * i + 1] = x[2 * i + 1] * di;
    }
}

__global__ void k_scatter(int E) {
    for (int e = blockIdx.x * blockDim.x + threadIdx.x; e < E;
         e += gridDim.x * blockDim.x) {
        int d = g_dst[e];
        int pos = atomicAdd(&g_cursor[d], 1);
        g_csr[pos] = g_src[e];
    }
}

// ---------------- layer 1: aggregate in input space (dim 2) ----------------

// cat[d] = [relu((dinv[d]*(sum xs[s] + xs[d])) @ W1 + b) (30), x[d] (2)]
__global__ void k_agg1(const float* __restrict__ x, const float* __restrict__ W1,
                       const float* __restrict__ b) {
    __shared__ float w[64];
    __shared__ float bb[32];
    if (threadIdx.x < 60) w[threadIdx.x] = W1[threadIdx.x];
    if (threadIdx.x < 30) bb[threadIdx.x] = b[threadIdx.x];
    __syncthreads();
    int d = (blockIdx.x * blockDim.x + threadIdx.x) >> 5;
    int lane = threadIdx.x & 31;
    if (d >= NN) return;
    int start = g_off[d], cnt = g_deg[d];
    float a0 = 0.f, a1 = 0.f;
    for (int i = lane; i < cnt; i += 32) {
        int s = g_csr[start + i];
        float2 v = ((const float2*)g_xs)[s];
        a0 += v.x; a1 += v.y;
    }
#pragma unroll
    for (int st = 16; st > 0; st >>= 1) {
        a0 += __shfl_xor_sync(0xffffffffu, a0, st);
        a1 += __shfl_xor_sync(0xffffffffu, a1, st);
    }
    float2 self = ((const float2*)g_xs)[d];
    float di = g_dinv[d];
    float s0 = (a0 + self.x) * di;
    float s1 = (a1 + self.y) * di;
    float out;
    if (lane < F) out = fmaxf(fmaf(s0, w[lane], fmaf(s1, w[30 + lane], bb[lane])), 0.f);
    else          out = x[2 * d + (lane - 30)];
    g_cat[d * FS + lane] = out;
}

// ---------------- layer 2 transform ----------------

// g = (cat @ W2) * dinv ;  cat:[N,32], W2:[32,30]
__global__ void k_t2(const float* __restrict__ W2) {
    __shared__ float w[32 * 30];
    for (int j = threadIdx.x; j < 960; j += blockDim.x) w[j] = W2[j];
    __syncthreads();
    int t = blockIdx.x * blockDim.x + threadIdx.x;
    if (t >= NN * FS) return;
    int i = t >> 5, f = t & 31;
    float v = 0.f;
    if (f < F) {
        const float* row = &g_cat[i * FS];
        float acc = 0.f;
#pragma unroll
        for (int k = 0; k < 32; k++) acc = fmaf(row[k], w[k * 30 + f], acc);
        v = acc * g_dinv[i];
    }
    g_feat[t] = v;
}

// layer-2 aggregation: warp per node over 128B rows of g_feat
__global__ void k_agg2(const float* __restrict__ x, const float* __restrict__ b) {
    int d = (blockIdx.x * blockDim.x + threadIdx.x) >> 5;
    int lane = threadIdx.x & 31;
    if (d >= NN) return;
    float acc = g_feat[d * FS + lane];   // self-loop term
    int start = g_off[d], cnt = g_deg[d];
    for (int e0 = 0; e0 < cnt; e0 += 32) {
        int idx = e0 + lane;
        int s = (idx < cnt) ? g_csr[start + idx] : 0;
        int m = min(32, cnt - e0);
        for (int j = 0; j < m; j++) {
            int sj = __shfl_sync(0xffffffffu, s, j);
            acc += g_feat[sj * FS + lane];
        }
    }
    float out;
    if (lane < F) out = fmaxf(fmaf(acc, g_dinv[d], b[lane]), 0.f);
    else          out = x[2 * d + (lane - 30)];
    g_cat[d * FS + lane] = out;
}

// ---------------- layer 3 ----------------

// g3 = (cat @ W3) * dinv ; W3:[32,1]
__global__ void k_t3(const float* __restrict__ W3) {
    __shared__ float w[32];
    if (threadIdx.x < 32) w[threadIdx.x] = W3[threadIdx.x];
    __syncthreads();
    int i = blockIdx.x * blockDim.x + threadIdx.x;
    if (i >= NN) return;
    const float* row = &g_cat[i * FS];
    float acc = 0.f;
#pragma unroll
    for (int k = 0; k < 32; k++) acc = fmaf(row[k], w[k], acc);
    g_scal[i] = acc * g_dinv[i];
}

__global__ void k_agg3(const float* __restrict__ b3, float* __restrict__ out) {
    int d = (blockIdx.x * blockDim.x + threadIdx.x) >> 5;
    int lane = threadIdx.x & 31;
    if (d >= NN) return;
    int start = g_off[d], cnt = g_deg[d];
    float acc = 0.f;
    for (int idx = lane; idx < cnt; idx += 32)
        acc += g_scal[g_csr[start + idx]];
#pragma unroll
    for (int st = 16; st > 0; st >>= 1)
        acc += __shfl_xor_sync(0xffffffffu, acc, st);
    if (lane == 0) out[d] = g_dinv[d] * (acc + g_scal[d]) + b3[0];
}

// ---------------- launch ----------------

extern "C" void kernel_launch(void* const* d_in, const int* in_sizes, int n_in,
                              void* d_out, int out_size) {
    const float* x  = (const float*)d_in[0];
    const void*  ei = d_in[1];
    const float* W1 = (const float*)d_in[2];
    const float* b1 = (const float*)d_in[3];
    const float* W2 = (const float*)d_in[4];
    const float* b2 = (const float*)d_in[5];
    const float* W3 = (const float*)d_in[6];
    const float* b3 = (const float*)d_in[7];
    float* out = (float*)d_out;

    int E = in_sizes[1] / 2;
    if (E > NE) E = NE;

    k_init<<<(NN + 255) / 256, 256>>>(ei, E);
    k_cvt_hist<<<2048, 256>>>(ei, E);
    k_bsum<<<NB, 256>>>();
    k_scansum<<<1, 32>>>(NB);
    k_scan<<<NB, CHUNK>>>(x);
    k_scatter<<<2048, 256>>>(E);

    int tN = (NN * FS + 255) / 256;       // transform grid (N*32 threads)
    int aN = (NN * 32 + 255) / 256;       // warp-per-node grid

    k_agg1<<<aN, 256>>>(x, W1, b1);       // layer 1 (input-space agg)
    k_t2<<<tN, 256>>>(W2);                // layer 2
    k_agg2<<<aN, 256>>>(x, b2);
    k_t3<<<(NN + 255) / 256, 256>>>(W3);  // layer 3
    k_agg3<<<aN, 256>>>(b3, out);
}

// round 4
// speedup vs baseline: 1.4100x; 1.2333x over previous
#include <cuda_runtime.h>

#define NN 200000
#define NE 3200000
#define F  30
#define FS 32          // padded feature stride (128B rows)
#define CHUNK 1024
#define NB ((NN + CHUNK - 1) / CHUNK)   // 196 scan blocks

// ---- scratch (device globals; no allocation allowed) ----
__device__ int   g_is64;
__device__ int   g_src[NE];
__device__ int   g_dst[NE];
__device__ int   g_deg[NN];
__device__ int   g_off[NN];
__device__ int   g_cursor[NN];
__device__ float g_dinv[NN];
__device__ float g_xs[NN * 2];      // x * dinv (layer-1 aggregation operand)
__device__ int   g_csr[NE];
__device__ float g_feat[NN * FS];   // layer-2 pre-scaled transformed features
__device__ float g_scal[NN];        // layer-3 scalar features
__device__ int   g_bsum[256];

// ---------------- init: zero degrees + dtype detect ----------------

__global__ void k_init(const void* __restrict__ ei, int E) {
    int i = blockIdx.x * blockDim.x + threadIdx.x;
    if (i < NN) g_deg[i] = 0;
    if (i == 0) {
        const long long* p = (const long long*)ei;
        int ok64 = 1;
        int n = (E < 64) ? E : 64;
        for (int k = 0; k < n; k++) {
            long long v = p[k];
            if (v < 0 || v >= NN) { ok64 = 0; break; }
        }
        g_is64 = ok64;
    }
}

// ---------------- fused convert + histogram ----------------

__global__ void k_cvt_hist(const void* __restrict__ ei, int E) {
    int is64 = g_is64;
    for (int e = blockIdx.x * blockDim.x + threadIdx.x; e < E;
         e += gridDim.x * blockDim.x) {
        int s, d;
        if (is64) {
            s = (int)((const long long*)ei)[e];
            d = (int)((const long long*)ei)[E + e];
        } else {
            s = ((const int*)ei)[e];
            d = ((const int*)ei)[E + e];
        }
        if ((unsigned)s >= NN) s = 0;
        if ((unsigned)d >= NN) d = 0;
        g_src[e] = s;
        g_dst[e] = d;
        atomicAdd(&g_deg[d], 1);
    }
}

// ---------------- block sums ----------------

__global__ void k_bsum() {   // grid NB, block 256
    __shared__ int sh[256];
    int base = blockIdx.x * CHUNK;
    int s = 0;
    for (int j = threadIdx.x; j < CHUNK; j += 256) {
        int i = base + j;
        if (i < NN) s += g_deg[i];
    }
    sh[threadIdx.x] = s;
    __syncthreads();
    for (int st = 128; st > 0; st >>= 1) {
        if (threadIdx.x < st) sh[threadIdx.x] += sh[threadIdx.x + st];
        __syncthreads();
    }
    if (threadIdx.x == 0) g_bsum[blockIdx.x] = sh[0];
}

// ---------------- scan: per-block prefix of bsum + chunk scan + dinv/xs ----

__global__ void k_scan(const float* __restrict__ x) {  // grid NB, block 1024
    __shared__ int sh[CHUNK];
    __shared__ int red[256];
    int t = threadIdx.x;

    // prefix of block sums (block b needs sum of g_bsum[0..b))
    if (t < 256) red[t] = (t < blockIdx.x && t < NB) ? g_bsum[t] : 0;
    __syncthreads();
    for (int st = 128; st > 0; st >>= 1) {
        if (t < st) red[t] += red[t + st];
        __syncthreads();
    }
    int base = red[0];

    // intra-chunk inclusive scan
    int i = blockIdx.x * CHUNK + t;
    int v = (i < NN) ? g_deg[i] : 0;
    sh[t] = v;
    __syncthreads();
    for (int st = 1; st < CHUNK; st <<= 1) {
        int tv = (t >= st) ? sh[t - st] : 0;
        __syncthreads();
        sh[t] += tv;
        __syncthreads();
    }
    if (i < NN) {
        int off = base + sh[t] - v;  // exclusive
        g_off[i] = off;
        g_cursor[i] = off;
        float di = rsqrtf((float)(v + 1));   // +1 self-loop
        g_dinv[i] = di;
        g_xs[2 * i]     = x[2 * i]     * di;
        g_xs[2 * i + 1] = x[2 * i + 1] * di;
    }
}

__global__ void k_scatter(int E) {
    for (int e = blockIdx.x * blockDim.x + threadIdx.x; e < E;
         e += gridDim.x * blockDim.x) {
        int d = g_dst[e];
        int pos = atomicAdd(&g_cursor[d], 1);
        g_csr[pos] = g_src[e];
    }
}

// ---------------- layer 1 agg (input space) + fused layer-2 transform ------

// cat[d] = [relu((dinv*(sum xs + xs[d])) @ W1 + b1) (30), x[d] (2)]   (registers)
// g_feat[d] = (cat[d] @ W2) * dinv[d]                                  (written)
__global__ void k_agg1(const float* __restrict__ x, const float* __restrict__ W1,
                       const float* __restrict__ b1, const float* __restrict__ W2) {
    __shared__ float w1[64];
    __shared__ float bb[32];
    __shared__ float w2[32 * 30];
    if (threadIdx.x < 60) w1[threadIdx.x] = W1[threadIdx.x];
    if (threadIdx.x < 30) bb[threadIdx.x] = b1[threadIdx.x];
    for (int j = threadIdx.x; j < 960; j += blockDim.x) w2[j] = W2[j];
    __syncthreads();

    int d = (blockIdx.x * blockDim.x + threadIdx.x) >> 5;
    int lane = threadIdx.x & 31;
    if (d >= NN) return;

    int start = g_off[d], cnt = g_deg[d];
    float a0 = 0.f, a1 = 0.f;
    for (int i = lane; i < cnt; i += 32) {
        int s = g_csr[start + i];
        float2 v = ((const float2*)g_xs)[s];
        a0 += v.x; a1 += v.y;
    }
#pragma unroll
    for (int st = 16; st > 0; st >>= 1) {
        a0 += __shfl_xor_sync(0xffffffffu, a0, st);
        a1 += __shfl_xor_sync(0xffffffffu, a1, st);
    }
    float2 self = ((const float2*)g_xs)[d];
    float di = g_dinv[d];
    float s0 = (a0 + self.x) * di;
    float s1 = (a1 + self.y) * di;

    float cat;
    if (lane < F) cat = fmaxf(fmaf(s0, w1[lane], fmaf(s1, w1[30 + lane], bb[lane])), 0.f);
    else          cat = x[2 * d + (lane - 30)];

    // fused layer-2 transform: g_feat[d,f] = (sum_k cat[k]*W2[k,f]) * dinv
    float acc = 0.f;
#pragma unroll
    for (int k = 0; k < 32; k++) {
        float ck = __shfl_sync(0xffffffffu, cat, k);
        if (lane < F) acc = fmaf(ck, w2[k * 30 + lane], acc);
    }
    g_feat[d * FS + lane] = (lane < F) ? acc * di : 0.f;
}

// ---------------- layer 2 agg + fused layer-3 transform ----------------

// cat2[d] = [relu(dinv*(sum g_feat[s] + g_feat[d]) + b2) (30), x[d] (2)]  (regs)
// g_scal[d] = (cat2[d] @ W3) * dinv[d]                                     (written)
__global__ void k_agg2(const float* __restrict__ x, const float* __restrict__ b2,
                       const float* __restrict__ W3) {
    __shared__ float bb[32];
    __shared__ float w3[32];
    if (threadIdx.x < 30) bb[threadIdx.x] = b2[threadIdx.x];
    if (threadIdx.x < 32) w3[threadIdx.x] = W3[threadIdx.x];
    __syncthreads();

    int d = (blockIdx.x * blockDim.x + threadIdx.x) >> 5;
    int lane = threadIdx.x & 31;
    if (d >= NN) return;

    float acc = g_feat[d * FS + lane];   // self-loop term
    int start = g_off[d], cnt = g_deg[d];
    for (int e0 = 0; e0 < cnt; e0 += 32) {
        int idx = e0 + lane;
        int s = (idx < cnt) ? g_csr[start + idx] : 0;
        int m = min(32, cnt - e0);
        for (int j = 0; j < m; j++) {
            int sj = __shfl_sync(0xffffffffu, s, j);
            acc += g_feat[sj * FS + lane];
        }
    }
    float di = g_dinv[d];
    float cat;
    if (lane < F) cat = fmaxf(fmaf(acc, di, bb[lane]), 0.f);
    else          cat = x[2 * d + (lane - 30)];

    // fused layer-3 transform: dot(cat2, W3) * dinv
    float p = cat * w3[lane];
#pragma unroll
    for (int st = 16; st > 0; st >>= 1)
        p += __shfl_xor_sync(0xffffffffu, p, st);
    if (lane == 0) g_scal[d] = p * di;
}

// ---------------- layer 3 aggregation ----------------

__global__ void k_agg3(const float* __restrict__ b3, float* __restrict__ out) {
    int d = (blockIdx.x * blockDim.x + threadIdx.x) >> 5;
    int lane = threadIdx.x & 31;
    if (d >= NN) return;
    int start = g_off[d], cnt = g_deg[d];
    float acc = 0.f;
    for (int idx = lane; idx < cnt; idx += 32)
        acc += g_scal[g_csr[start + idx]];
#pragma unroll
    for (int st = 16; st > 0; st >>= 1)
        acc += __shfl_xor_sync(0xffffffffu, acc, st);
    if (lane == 0) out[d] = g_dinv[d] * (acc + g_scal[d]) + b3[0];
}

// ---------------- launch ----------------

extern "C" void kernel_launch(void* const* d_in, const int* in_sizes, int n_in,
                              void* d_out, int out_size) {
    const float* x  = (const float*)d_in[0];
    const void*  ei = d_in[1];
    const float* W1 = (const float*)d_in[2];
    const float* b1 = (const float*)d_in[3];
    const float* W2 = (const float*)d_in[4];
    const float* b2 = (const float*)d_in[5];
    const float* W3 = (const float*)d_in[6];
    const float* b3 = (const float*)d_in[7];
    float* out = (float*)d_out;

    int E = in_sizes[1] / 2;
    if (E > NE) E = NE;

    k_init<<<(NN + 255) / 256, 256>>>(ei, E);
    k_cvt_hist<<<2048, 256>>>(ei, E);
    k_bsum<<<NB, 256>>>();
    k_scan<<<NB, CHUNK>>>(x);
    k_scatter<<<2048, 256>>>(E);

    int aN = (NN * 32 + 255) / 256;       // warp-per-node grid

    k_agg1<<<aN, 256>>>(x, W1, b1, W2);   // layer 1 agg + layer 2 transform
    k_agg2<<<aN, 256>>>(x, b2, W3);       // layer 2 agg + layer 3 transform
    k_agg3<<<aN, 256>>>(b3, out);         // layer 3 agg -> output
}

// round 5
// speedup vs baseline: 1.4670x; 1.0404x over previous
#include <cuda_runtime.h>
#include <cuda_fp16.h>

#define NN 200000
#define NE 3200000
#define F  30
#define FS 32          // padded feature stride
#define CHUNK 1024
#define NB ((NN + CHUNK - 1) / CHUNK)   // 196 scan blocks

// ---- scratch (device globals; no allocation allowed) ----
__device__ int    g_is64;
__device__ int    g_src[NE];
__device__ int    g_dst[NE];
__device__ int    g_deg[NN];
__device__ int    g_off[NN];
__device__ int    g_cursor[NN];
__device__ float  g_dinv[NN];
__device__ float  g_xs[NN * 2];      // x * dinv (layer-1 aggregation operand)
__device__ int    g_csr[NE];
__device__ __half g_feat[NN * FS];   // layer-2 pre-scaled features (fp16, 64B rows)
__device__ float  g_scal[NN];        // layer-3 scalar features
__device__ int    g_bsum[256];

// ---------------- init: zero degrees + dtype detect ----------------

__global__ void k_init(const void* __restrict__ ei, int E) {
    int i = blockIdx.x * blockDim.x + threadIdx.x;
    if (i < NN) g_deg[i] = 0;
    if (i == 0) {
        const long long* p = (const long long*)ei;
        int ok64 = 1;
        int n = (E < 64) ? E : 64;
        for (int k = 0; k < n; k++) {
            long long v = p[k];
            if (v < 0 || v >= NN) { ok64 = 0; break; }
        }
        g_is64 = ok64;
    }
}

// ---------------- fused convert + histogram ----------------

__global__ void k_cvt_hist(const void* __restrict__ ei, int E) {
    int is64 = g_is64;
    for (int e = blockIdx.x * blockDim.x + threadIdx.x; e < E;
         e += gridDim.x * blockDim.x) {
        int s, d;
        if (is64) {
            s = (int)((const long long*)ei)[e];
            d = (int)((const long long*)ei)[E + e];
        } else {
            s = ((const int*)ei)[e];
            d = ((const int*)ei)[E + e];
        }
        if ((unsigned)s >= NN) s = 0;
        if ((unsigned)d >= NN) d = 0;
        g_src[e] = s;
        g_dst[e] = d;
        atomicAdd(&g_deg[d], 1);
    }
}

// ---------------- block sums ----------------

__global__ void k_bsum() {   // grid NB, block 256
    __shared__ int sh[256];
    int base = blockIdx.x * CHUNK;
    int s = 0;
    for (int j = threadIdx.x; j < CHUNK; j += 256) {
        int i = base + j;
        if (i < NN) s += g_deg[i];
    }
    sh[threadIdx.x] = s;
    __syncthreads();
    for (int st = 128; st > 0; st >>= 1) {
        if (threadIdx.x < st) sh[threadIdx.x] += sh[threadIdx.x + st];
        __syncthreads();
    }
    if (threadIdx.x == 0) g_bsum[blockIdx.x] = sh[0];
}

// ---------------- scan (warp-shuffle) + dinv/xs ----------------

__global__ void k_scan(const float* __restrict__ x) {  // grid NB, block 1024
    __shared__ int red[256];
    __shared__ int wsum[32];
    int t = threadIdx.x, lane = t & 31, w = t >> 5;

    // prefix of block sums (block b needs sum of g_bsum[0..b))
    if (t < 256) red[t] = (t < blockIdx.x) ? g_bsum[t] : 0;
    __syncthreads();
    for (int st = 128; st > 0; st >>= 1) {
        if (t < st) red[t] += red[t + st];
        __syncthreads();
    }
    int base = red[0];

    int i = blockIdx.x * CHUNK + t;
    int v = (i < NN) ? g_deg[i] : 0;

    // warp inclusive scan
    int s = v;
#pragma unroll
    for (int st = 1; st < 32; st <<= 1) {
        int u = __shfl_up_sync(0xffffffffu, s, st);
        if (lane >= st) s += u;
    }
    if (lane == 31) wsum[w] = s;
    __syncthreads();
    if (w == 0) {
        int ws = wsum[lane];
#pragma unroll
        for (int st = 1; st < 32; st <<= 1) {
            int u = __shfl_up_sync(0xffffffffu, ws, st);
            if (lane >= st) ws += u;
        }
        wsum[lane] = ws;
    }
    __syncthreads();
    int incl = s + (w > 0 ? wsum[w - 1] : 0);

    if (i < NN) {
        int off = base + incl - v;  // exclusive
        g_off[i] = off;
        g_cursor[i] = off;
        float di = rsqrtf((float)(v + 1));   // +1 self-loop
        g_dinv[i] = di;
        g_xs[2 * i]     = x[2 * i]     * di;
        g_xs[2 * i + 1] = x[2 * i + 1] * di;
    }
}

__global__ void k_scatter(int E) {
    for (int e = blockIdx.x * blockDim.x + threadIdx.x; e < E;
         e += gridDim.x * blockDim.x) {
        int d = g_dst[e];
        int pos = atomicAdd(&g_cursor[d], 1);
        g_csr[pos] = g_src[e];
    }
}

// ---------------- layer 1 agg (input space) + fused layer-2 transform ------

// cat[d] = [relu((dinv*(sum xs + xs[d])) @ W1 + b1) (30), x[d] (2)]   (registers)
// g_feat[d] = fp16( (cat[d] @ W2) * dinv[d] )                          (written)
__global__ void k_agg1(const float* __restrict__ x, const float* __restrict__ W1,
                       const float* __restrict__ b1, const float* __restrict__ W2) {
    __shared__ float w1[64];
    __shared__ float bb[32];
    __shared__ float w2[32 * 30];
    if (threadIdx.x < 60) w1[threadIdx.x] = W1[threadIdx.x];
    if (threadIdx.x < 30) bb[threadIdx.x] = b1[threadIdx.x];
    for (int j = threadIdx.x; j < 960; j += blockDim.x) w2[j] = W2[j];
    __syncthreads();

    int d = (blockIdx.x * blockDim.x + threadIdx.x) >> 5;
    int lane = threadIdx.x & 31;
    if (d >= NN) return;

    int start = g_off[d], cnt = g_deg[d];
    float a0 = 0.f, a1 = 0.f;
    for (int i = lane; i < cnt; i += 32) {
        int s = g_csr[start + i];
        float2 v = ((const float2*)g_xs)[s];
        a0 += v.x; a1 += v.y;
    }
#pragma unroll
    for (int st = 16; st > 0; st >>= 1) {
        a0 += __shfl_xor_sync(0xffffffffu, a0, st);
        a1 += __shfl_xor_sync(0xffffffffu, a1, st);
    }
    float2 self = ((const float2*)g_xs)[d];
    float di = g_dinv[d];
    float s0 = (a0 + self.x) * di;
    float s1 = (a1 + self.y) * di;

    float cat;
    if (lane < F) cat = fmaxf(fmaf(s0, w1[lane], fmaf(s1, w1[30 + lane], bb[lane])), 0.f);
    else          cat = x[2 * d + (lane - 30)];

    // fused layer-2 transform: g_feat[d,f] = fp16((sum_k cat[k]*W2[k,f]) * dinv)
    float acc = 0.f;
#pragma unroll
    for (int k = 0; k < 32; k++) {
        float ck = __shfl_sync(0xffffffffu, cat, k);
        if (lane < F) acc = fmaf(ck, w2[k * 30 + lane], acc);
    }
    g_feat[d * FS + lane] = __float2half((lane < F) ? acc * di : 0.f);
}

// ---------------- layer 2 agg + fused layer-3 transform ----------------

// cat2[d] = [relu(dinv*(sum g_feat[s] + g_feat[d]) + b2) (30), x[d] (2)]  (regs)
// g_scal[d] = (cat2[d] @ W3) * dinv[d]                                     (written)
__global__ void k_agg2(const float* __restrict__ x, const float* __restrict__ b2,
                       const float* __restrict__ W3) {
    __shared__ float bb[32];
    __shared__ float w3[32];
    if (threadIdx.x < 30) bb[threadIdx.x] = b2[threadIdx.x];
    if (threadIdx.x < 32) w3[threadIdx.x] = W3[threadIdx.x];
    __syncthreads();

    int d = (blockIdx.x * blockDim.x + threadIdx.x) >> 5;
    int lane = threadIdx.x & 31;
    if (d >= NN) return;

    float acc = __half2float(g_feat[d * FS + lane]);   // self-loop term
    int start = g_off[d], cnt = g_deg[d];
    for (int e0 = 0; e0 < cnt; e0 += 32) {
        int idx = e0 + lane;
        int s = (idx < cnt) ? g_csr[start + idx] : 0;
        int m = min(32, cnt - e0);
        for (int j = 0; j < m; j++) {
            int sj = __shfl_sync(0xffffffffu, s, j);
            acc += __half2float(g_feat[sj * FS + lane]);
        }
    }
    float di = g_dinv[d];
    float cat;
    if (lane < F) cat = fmaxf(fmaf(acc, di, bb[lane]), 0.f);
    else          cat = x[2 * d + (lane - 30)];

    // fused layer-3 transform: dot(cat2, W3) * dinv
    float p = cat * w3[lane];
#pragma unroll
    for (int st = 16; st > 0; st >>= 1)
        p += __shfl_xor_sync(0xffffffffu, p, st);
    if (lane == 0) g_scal[d] = p * di;
}

// ---------------- layer 3 aggregation (half-warp per node) ----------------

__global__ void k_agg3(const float* __restrict__ b3, float* __restrict__ out) {
    int d = (blockIdx.x * blockDim.x + threadIdx.x) >> 4;
    int lane = threadIdx.x & 15;
    if (d >= NN) return;
    int start = g_off[d], cnt = g_deg[d];
    float acc = 0.f;
    for (int idx = lane; idx < cnt; idx += 16)
        acc += g_scal[g_csr[start + idx]];
#pragma unroll
    for (int st = 8; st > 0; st >>= 1)
        acc += __shfl_xor_sync(0xffffffffu, acc, st);
    if (lane == 0) out[d] = g_dinv[d] * (acc + g_scal[d]) + b3[0];
}

// ---------------- launch ----------------

extern "C" void kernel_launch(void* const* d_in, const int* in_sizes, int n_in,
                              void* d_out, int out_size) {
    const float* x  = (const float*)d_in[0];
    const void*  ei = d_in[1];
    const float* W1 = (const float*)d_in[2];
    const float* b1 = (const float*)d_in[3];
    const float* W2 = (const float*)d_in[4];
    const float* b2 = (const float*)d_in[5];
    const float* W3 = (const float*)d_in[6];
    const float* b3 = (const float*)d_in[7];
    float* out = (float*)d_out;

    int E = in_sizes[1] / 2;
    if (E > NE) E = NE;

    k_init<<<(NN + 255) / 256, 256>>>(ei, E);
    k_cvt_hist<<<2048, 256>>>(ei, E);
    k_bsum<<<NB, 256>>>();
    k_scan<<<NB, CHUNK>>>(x);
    k_scatter<<<2048, 256>>>(E);

    int aN  = (NN * 32 + 255) / 256;      // warp-per-node grid
    int a3N = (NN * 16 + 255) / 256;      // half-warp-per-node grid

    k_agg1<<<aN, 256>>>(x, W1, b1, W2);   // layer 1 agg + layer 2 transform
    k_agg2<<<aN, 256>>>(x, b2, W3);       // layer 2 agg + layer 3 transform
    k_agg3<<<a3N, 256>>>(b3, out);        // layer 3 agg -> output
}